// round 15
// baseline (speedup 1.0000x reference)
#include <cuda_runtime.h>
#include <math.h>

#define B_  32
#define NH  778
#define NO  3000
#define Z_  64
#define NPRIOR 204

#define NT_PAD      800
#define FUS_SEGS    8
#define FUS_SEGLEN  100
#define FUS_CHUNKS  3          // 3*1024 = 3072 >= 3000 (4 queries/thread)
#define FUS_ITEMS   (FUS_SEGS * FUS_CHUNKS * B_)    // 768
#define PRIOR_PAD   208
#define PRIOR_ITEMS (FUS_CHUNKS * B_)               // 96 (first: longest blocks)
#define TOTAL_ITEMS (FUS_ITEMS + PRIOR_ITEMS)       // 864

#define QPT 12   // obj-epi queries per thread (12*256 = 3072 >= 3000)

// Merged via atomicMax(~bits): zero = identity; consumers reset to 0 for replay.
__device__ unsigned g_okr[B_ * NO];
__device__ unsigned g_okg[B_ * NO];
__device__ float    g_mp[B_ * NO];
__device__ unsigned g_cmr[B_ * NT_PAD];
__device__ unsigned g_cmg[B_ * NT_PAD];
// 0 penetr, 1 npts, 2 contact, 3 consist, 4 loss_o, 5 loss_h, 6 mse, 7 kld
__device__ double   g_acc[8];
__device__ unsigned g_ctr;

__constant__ int c_prior[NPRIOR] = {
  697,698,699,700,712,713,714,715,737,738,739,740,741,743,744,745,
  746,748,749,750,753,754,755,756,757,758,759,760,761,762,763,764,
  765,766,767,768,
  46,47,48,49,164,165,166,167,194,195,223,237,238,280,281,298,
  301,317,320,323,324,325,326,327,328,329,330,331,332,333,340,341,
  342,343,344,345,346,347,348,349,350,351,352,353,354,355,
  356,357,358,359,375,376,386,387,396,397,402,403,413,429,433,434,
  435,436,437,438,439,440,441,442,443,444,452,453,454,455,456,459,
  460,461,462,463,464,465,466,467,
  468,469,470,471,484,485,486,496,497,506,507,513,514,524,545,546,
  547,548,549,550,551,552,553,555,563,564,565,566,567,570,572,573,
  574,575,576,577,578,
  580,581,582,583,600,601,602,614,615,624,625,630,631,641,663,664,
  665,666,667,668,670,672,680,681,682,683,684,686,687,688,689,690,
  691,692,693,694,695,
  73,96,98,99,772,774,775,777
};

typedef unsigned long long u64;

__device__ __forceinline__ u64 fma2(u64 a, u64 b, u64 c) {
    u64 d;
    asm("fma.rn.f32x2 %0, %1, %2, %3;" : "=l"(d) : "l"(a), "l"(b), "l"(c));
    return d;
}
__device__ __forceinline__ u64 add2(u64 a, u64 b) {
    u64 d;
    asm("add.rn.f32x2 %0, %1, %2;" : "=l"(d) : "l"(a), "l"(b));
    return d;
}
__device__ __forceinline__ u64 pack2(float lo, float hi) {
    u64 d;
    asm("mov.b64 %0, {%1, %2};" : "=l"(d) : "r"(__float_as_uint(lo)), "r"(__float_as_uint(hi)));
    return d;
}
__device__ __forceinline__ void unpack2u(u64 v, unsigned& lo, unsigned& hi) {
    asm("mov.b64 {%0, %1}, %2;" : "=r"(lo), "=r"(hi) : "l"(v));
}
__device__ __forceinline__ float warp_sum(float v) {
#pragma unroll
    for (int o = 16; o > 0; o >>= 1) v += __shfl_down_sync(0xffffffffu, v, o);
    return v;
}
__device__ __forceinline__ float sgnf(float x) {
    return (x > 0.f) ? 1.f : ((x < 0.f) ? -1.f : 0.f);
}

__global__ void __launch_bounds__(256, 3) k_main(
    const float* __restrict__ recon, const float* __restrict__ gt,
    const float* __restrict__ obj)
{
    __shared__ __align__(16) u64 T[PRIOR_PAD][4];
    __shared__ __align__(8) uint2 s_cm[8][FUS_SEGLEN];
    const int tid = threadIdx.x;
    const int lane = tid & 31, warp = tid >> 5;
    const float FINF = __int_as_float(0x7F800000);
    const int item = blockIdx.x;

    if (item >= PRIOR_ITEMS) {
        // ===== FUSED: row argmin + col min, 4 queries/thread =====
        const int fit   = item - PRIOR_ITEMS;
        const int seg   = fit & 7;
        const int rest  = fit >> 3;
        const int chunk = rest % FUS_CHUNKS;
        const int b     = rest / FUS_CHUNKS;

        int  jq[4];
        bool aq[4];
        u64 BQ[4], NX[4], NY[4], NZ[4];
        const float* ob = obj + (size_t)b * NO * 3;
#pragma unroll
        for (int q = 0; q < 4; q++) {
            const int j = chunk * 1024 + q * 256 + tid;
            jq[q] = j;
            aq[q] = (j < NO);
            const int jj = aq[q] ? j : (NO - 1);
            const float ox = ob[3*jj], oy = ob[3*jj+1], oz = ob[3*jj+2];
            const float bq = 0.5f*(ox*ox + oy*oy + oz*oz);
            BQ[q] = pack2(bq, bq);
            NX[q] = pack2(-ox, -ox);
            NY[q] = pack2(-oy, -oy);
            NZ[q] = pack2(-oz, -oz);
        }

        const float* rb = recon + (size_t)b * NH * 3;
        const float* gb = gt    + (size_t)b * NH * 3;
        const int t0 = seg * FUS_SEGLEN;

        if (tid < FUS_SEGLEN) {
            const int tg = t0 + tid;
            float rx=0.f, ry=0.f, rz=0.f, rw=FINF, gx=0.f, gy=0.f, gz=0.f, gw=FINF;
            if (tg < NH) {
                rx = rb[3*tg]; ry = rb[3*tg+1]; rz = rb[3*tg+2];
                rw = 0.5f*(rx*rx + ry*ry + rz*rz);
                gx = gb[3*tg]; gy = gb[3*tg+1]; gz = gb[3*tg+2];
                gw = 0.5f*(gx*gx + gy*gy + gz*gz);
            }
            float2* pp = (float2*)T[tid];
            pp[0] = make_float2(rx, gx); pp[1] = make_float2(ry, gy);
            pp[2] = make_float2(rz, gz); pp[3] = make_float2(rw, gw);
        }
        __syncthreads();

        unsigned br[4] = {0xFFFFFFFFu, 0xFFFFFFFFu, 0xFFFFFFFFu, 0xFFFFFFFFu};
        unsigned bg[4] = {0xFFFFFFFFu, 0xFFFFFFFFu, 0xFFFFFFFFu, 0xFFFFFFFFu};
#pragma unroll 4
        for (int k = 0; k < FUS_SEGLEN; k++) {
            const ulonglong2 A  = *(const ulonglong2*)&T[k][0];
            const ulonglong2 Bv = *(const ulonglong2*)&T[k][2];
            const unsigned kb = (unsigned)(t0 + k);
            unsigned cr = 0xFFFFFFFFu, cg = 0xFFFFFFFFu;
#pragma unroll
            for (int q = 0; q < 4; q++) {
                u64 M = add2(BQ[q], Bv.y);
                M = fma2(NX[q], A.x, M); M = fma2(NY[q], A.y, M); M = fma2(NZ[q], Bv.x, M);
                unsigned r, g; unpack2u(M, r, g);
                br[q] = min(br[q], (r & 0xFFFFFC00u) | kb);
                bg[q] = min(bg[q], (g & 0xFFFFFC00u) | kb);
                cr = min(cr, r);
                cg = min(cg, g);
            }
            unsigned wr = __reduce_min_sync(0xffffffffu, cr);
            unsigned wg = __reduce_min_sync(0xffffffffu, cg);
            if (lane == 0) s_cm[warp][k] = make_uint2(wr, wg);
        }
#pragma unroll
        for (int q = 0; q < 4; q++) {
            if (aq[q]) {
                atomicMax(&g_okr[b * NO + jq[q]], ~br[q]);
                atomicMax(&g_okg[b * NO + jq[q]], ~bg[q]);
            }
        }

        __syncthreads();
        if (tid < FUS_SEGLEN) {
            uint2 m = s_cm[0][tid];
#pragma unroll
            for (int w = 1; w < 8; w++) {
                uint2 v = s_cm[w][tid];
                m.x = min(m.x, v.x);
                m.y = min(m.y, v.y);
            }
            const int base = b * NT_PAD + t0 + tid;
            atomicMax(&g_cmr[base], ~m.x);
            atomicMax(&g_cmg[base], ~m.y);
        }
    } else {
        // ===== PRIOR: 204 targets, 1024 queries (4/thread) =====
        const int idx   = item;
        const int chunk = idx % FUS_CHUNKS;
        const int b     = idx / FUS_CHUNKS;

        int  jq[4];
        bool aq[4];
        float oxq[4], oyq[4], ozq[4], bqq[4];
        const float* ob = obj + (size_t)b * NO * 3;
#pragma unroll
        for (int q = 0; q < 4; q++) {
            const int j = chunk * 1024 + q * 256 + tid;
            jq[q] = j;
            aq[q] = (j < NO);
            const int jj = aq[q] ? j : (NO - 1);
            oxq[q] = ob[3*jj]; oyq[q] = ob[3*jj+1]; ozq[q] = ob[3*jj+2];
            bqq[q] = 0.5f*(oxq[q]*oxq[q] + oyq[q]*oyq[q] + ozq[q]*ozq[q]);
        }
        const u64 BQ01 = pack2(bqq[0], bqq[1]), NX01 = pack2(-oxq[0], -oxq[1]),
                  NY01 = pack2(-oyq[0], -oyq[1]), NZ01 = pack2(-ozq[0], -ozq[1]);
        const u64 BQ23 = pack2(bqq[2], bqq[3]), NX23 = pack2(-oxq[2], -oxq[3]),
                  NY23 = pack2(-oyq[2], -oyq[3]), NZ23 = pack2(-ozq[2], -ozq[3]);

        const float* rb = recon + (size_t)b * NH * 3;
        if (tid < PRIOR_PAD) {
            float x = 0.f, y = 0.f, z = 0.f, w = FINF;
            if (tid < NPRIOR) {
                const int p = c_prior[tid];
                x = rb[3*p]; y = rb[3*p+1]; z = rb[3*p+2];
                w = 0.5f*(x*x + y*y + z*z);
            }
            float2* pp = (float2*)T[tid];
            pp[0] = make_float2(x, x); pp[1] = make_float2(y, y);
            pp[2] = make_float2(z, z); pp[3] = make_float2(w, w);
        }
        __syncthreads();

        float mp[4] = {FINF, FINF, FINF, FINF};
#pragma unroll 8
        for (int k = 0; k < PRIOR_PAD; k++) {
            const ulonglong2 A  = *(const ulonglong2*)&T[k][0];
            const ulonglong2 Bv = *(const ulonglong2*)&T[k][2];
            u64 M = add2(BQ01, Bv.y);
            M = fma2(NX01, A.x, M); M = fma2(NY01, A.y, M); M = fma2(NZ01, Bv.x, M);
            unsigned u0, u1; unpack2u(M, u0, u1);
            mp[0] = fminf(mp[0], __uint_as_float(u0));
            mp[1] = fminf(mp[1], __uint_as_float(u1));
            M = add2(BQ23, Bv.y);
            M = fma2(NX23, A.x, M); M = fma2(NY23, A.y, M); M = fma2(NZ23, Bv.x, M);
            unpack2u(M, u0, u1);
            mp[2] = fminf(mp[2], __uint_as_float(u0));
            mp[3] = fminf(mp[3], __uint_as_float(u1));
        }
#pragma unroll
        for (int q = 0; q < 4; q++)
            if (aq[q]) g_mp[b * NO + jq[q]] = mp[q];
    }
}

// ===== Epilogue: 32 blocks, one per batch; hand arrays staged in smem. =====
__global__ void __launch_bounds__(256) k_epi(
    const float* __restrict__ recon, const float* __restrict__ gt,
    const float* __restrict__ recon_n, const float* __restrict__ gt_n,
    const float* __restrict__ obj,
    const float* __restrict__ mean, const float* __restrict__ logv,
    const float* __restrict__ vw, float* __restrict__ out)
{
    __shared__ float s_rb[NH * 3];
    __shared__ float s_gb[NH * 3];
    __shared__ float s_rn[NH * 3];
    __shared__ float s_gn[NH * 3];
    __shared__ float red[8][8];
    __shared__ bool s_last;

    const int tid = threadIdx.x;
    const int b = blockIdx.x;
    const int lane = tid & 31, warp = tid >> 5;

    const float* rb  = recon   + (size_t)b * NH * 3;
    const float* gb  = gt      + (size_t)b * NH * 3;
    const float* rnb = recon_n + (size_t)b * NH * 3;
    const float* gnb = gt_n    + (size_t)b * NH * 3;
    const float* ob  = obj     + (size_t)b * NO * 3;

    for (int i = tid; i < NH * 3; i += 256) {
        s_rb[i] = rb[i];
        s_gb[i] = gb[i];
        s_rn[i] = rnb[i];
        s_gn[i] = gnb[i];
    }
    __syncthreads();

    // a: penetr, npts, contact, consist, loss_o, loss_h, mse, kld
    float a[8] = {0.f,0.f,0.f,0.f,0.f,0.f,0.f,0.f};

    // ---- MSE from staged arrays ----
    for (int i = tid; i < NH * 3; i += 256) {
        float d = s_rb[i] - s_gb[i];
        a[6] += d * d;
    }
    // ---- KLD slice (64 per batch) ----
    if (tid < Z_) {
        const int q = b * Z_ + tid;
        float m = mean[q], lv = logv[q];
        a[7] = 1.f + lv - m * m - expf(lv);
    }

    // ---- obj epilogue: preload keys/coords (one MLP round), gathers from smem ----
    unsigned kr[QPT], kg[QPT];
    float mpv[QPT];
    float qx[QPT], qy[QPT], qz[QPT];
#pragma unroll
    for (int q = 0; q < QPT; q++) {
        const int j = q * 256 + tid;
        if (j < NO) {
            const int idx = b * NO + j;
            kr[q] = g_okr[idx];
            kg[q] = g_okg[idx];
            mpv[q] = g_mp[idx];
            qx[q] = ob[3*j]; qy[q] = ob[3*j+1]; qz[q] = ob[3*j+2];
        }
    }
#pragma unroll
    for (int q = 0; q < QPT; q++) {
        const int j = q * 256 + tid;
        if (j >= NO) continue;
        const int idx = b * NO + j;
        g_okr[idx] = 0u;
        g_okg[idx] = 0u;
        const unsigned br = ~kr[q];
        const unsigned bg = ~kg[q];
        const int ir = (int)(br & 1023u);
        const int ig = (int)(bg & 1023u);
        const float ox = qx[q], oy = qy[q], oz = qz[q];

        float dxr = ox - s_rb[3*ir], dyr = oy - s_rb[3*ir+1], dzr = oz - s_rb[3*ir+2];
        float d2r = dxr*dxr + dyr*dyr + dzr*dzr;
        float dotr = s_rn[3*ir]*dxr + s_rn[3*ir+1]*dyr + s_rn[3*ir+2]*dzr;
        float o2h = sqrtf(d2r) * sgnf(dotr);
        bool interior = (-dotr) > 0.f;

        float dxg = ox - s_gb[3*ig], dyg = oy - s_gb[3*ig+1], dzg = oz - s_gb[3*ig+2];
        float d2g = dxg*dxg + dyg*dyg + dzg*dzg;
        float dotg = s_gn[3*ig]*dxg + s_gn[3*ig+1]*dyg + s_gn[3*ig+2]*dzg;
        float o2h_gt = sqrtf(d2g) * sgnf(dotg);

        float d2p = fmaxf(2.f * mpv[q], 0.f);
        bool cmap  = sqrtf(d2g) < 0.005f;
        bool rcmap = sqrtf(d2r) < 0.005f;

        a[0] += interior ? d2r : 0.f;
        a[1] += cmap ? 1.f : 0.f;
        a[2] += cmap ? d2p : 0.f;
        a[3] += (cmap && rcmap) ? 1.f : 0.f;
        bool w_dist = (o2h_gt < 0.01f) && (o2h_gt > -0.005f);
        float w = (o2h < 0.f) ? 1.5f : (w_dist ? 1.0f : 0.1f);
        a[4] += fabsf(o2h - o2h_gt) * w;
    }

    // ---- hand epilogue ----
#pragma unroll
    for (int p = 0; p < 4; p++) {
        const int i = p * 256 + tid;
        if (i >= NT_PAD) continue;
        const int base = b * NT_PAD + i;
        unsigned umr = g_cmr[base], umg = g_cmg[base];
        g_cmr[base] = 0u;
        g_cmg[base] = 0u;
        if (i < NH) {
            float mr = __uint_as_float(~umr);
            float mg = __uint_as_float(~umg);
            float dr = sqrtf(fmaxf(2.f * mr, 0.f));
            float dg = sqrtf(fmaxf(2.f * mg, 0.f));
            a[5] += fabsf(dr - dg) * powf(vw[i], 0.4f);
        }
    }

    // ---- block reduce + global accumulate ----
#pragma unroll
    for (int q = 0; q < 8; q++) {
        float v = warp_sum(a[q]);
        if (lane == 0) red[warp][q] = v;
    }
    __syncthreads();
    if (tid < 8) {
        float s = 0.f;
#pragma unroll
        for (int wi = 0; wi < 8; wi++) s += red[wi][tid];
        atomicAdd(&g_acc[tid], (double)s);
    }

    if (tid == 0) {
        __threadfence();
        unsigned t = atomicAdd(&g_ctr, 1u);
        s_last = (t == (unsigned)(gridDim.x - 1));
    }
    __syncthreads();

    if (s_last && tid == 0) {
        __threadfence();
        const double KLC = 0.005;
        double recon_loss = g_acc[6] / B_;
        double kld        = -0.5 * g_acc[7] / B_ * 10.0;
        double penetr     = 100.0 * g_acc[0] / B_;
        double npts       = g_acc[1];
        double contact    = 3000.0 * ((npts > 0.0) ? (g_acc[2] / (B_ * npts)) : 0.0);
        double consist    = -5.0 * g_acc[3] / (npts + 0.0001);
        double loss_o     = 30.0 * (1.0 - KLC) * g_acc[4] / ((double)B_ * NO);
        double loss_h     = 35.0 * (1.0 - KLC) * g_acc[5] / ((double)B_ * NH);
        double total = recon_loss + 0.1 * kld + 1000.0 * penetr
                     + 10.0 * contact + 10.0 * consist + (loss_h + loss_o);
        out[0] = (float)total;
#pragma unroll
        for (int q = 0; q < 8; q++) g_acc[q] = 0.0;
        g_ctr = 0u;
    }
}

extern "C" void kernel_launch(void* const* d_in, const int* in_sizes, int n_in,
                              void* d_out, int out_size) {
    const float* recon   = (const float*)d_in[0];
    const float* gt      = (const float*)d_in[1];
    const float* recon_n = (const float*)d_in[2];
    const float* gt_n    = (const float*)d_in[3];
    const float* obj     = (const float*)d_in[4];
    const float* mean    = (const float*)d_in[5];
    const float* logv    = (const float*)d_in[6];
    const float* vw      = (const float*)d_in[7];
    float* out = (float*)d_out;

    k_main<<<TOTAL_ITEMS, 256>>>(recon, gt, obj);
    k_epi<<<B_, 256>>>(recon, gt, recon_n, gt_n, obj, mean, logv, vw, out);
}

// round 16
// speedup vs baseline: 1.0726x; 1.0726x over previous
#include <cuda_runtime.h>
#include <math.h>

#define B_  32
#define NH  778
#define NO  3000
#define Z_  64
#define NPRIOR 204

#define NT_PAD      800
#define FUS_SEGS    8
#define FUS_SEGLEN  100
#define FUS_CHUNKS  3          // 3*1024 = 3072 >= 3000 (4 queries/thread)
#define FUS_ITEMS   (FUS_SEGS * FUS_CHUNKS * B_)    // 768
#define PRIOR_PAD   208
#define PRIOR_ITEMS (FUS_CHUNKS * B_)               // 96 (first: longest blocks)
#define SCAN_ITEMS  (FUS_ITEMS + PRIOR_ITEMS)       // 864

#define OBJ_EPI_ITEMS  (B_ * FUS_CHUNKS)            // 96
#define HAND_EPI_ITEMS B_                           // 32
#define EPI_ITEMS      (OBJ_EPI_ITEMS + HAND_EPI_ITEMS)  // 128
#define TOTAL_ITEMS    (SCAN_ITEMS + EPI_ITEMS)     // 992

#define MSE_ITEMS   ((B_ * NH * 3) / 4)             // 18672 float4
#define MSE_PER_BLK 195                             // 195*96 >= 18672
#define KLD_PER_BLK 22                              // 22*96 >= 2048

// Merged via atomicMax(~bits): zero = identity; consumers reset to 0 for replay.
__device__ unsigned g_okr[B_ * NO];
__device__ unsigned g_okg[B_ * NO];
__device__ float    g_mp[B_ * NO];
__device__ unsigned g_cmr[B_ * NT_PAD];
__device__ unsigned g_cmg[B_ * NT_PAD];
// 0 penetr, 1 npts, 2 contact, 3 consist, 4 loss_o, 5 loss_h, 6 mse, 7 kld
__device__ double   g_acc[8];
__device__ unsigned g_done_chunk[B_ * FUS_CHUNKS];  // -> 9 (8 segs + prior); reset by consumer
__device__ unsigned g_done_batch[B_];               // -> 24 (fused); reset by consumer
__device__ unsigned g_ctr;                          // -> EPI_ITEMS; self-reset

__constant__ int c_prior[NPRIOR] = {
  697,698,699,700,712,713,714,715,737,738,739,740,741,743,744,745,
  746,748,749,750,753,754,755,756,757,758,759,760,761,762,763,764,
  765,766,767,768,
  46,47,48,49,164,165,166,167,194,195,223,237,238,280,281,298,
  301,317,320,323,324,325,326,327,328,329,330,331,332,333,340,341,
  342,343,344,345,346,347,348,349,350,351,352,353,354,355,
  356,357,358,359,375,376,386,387,396,397,402,403,413,429,433,434,
  435,436,437,438,439,440,441,442,443,444,452,453,454,455,456,459,
  460,461,462,463,464,465,466,467,
  468,469,470,471,484,485,486,496,497,506,507,513,514,524,545,546,
  547,548,549,550,551,552,553,555,563,564,565,566,567,570,572,573,
  574,575,576,577,578,
  580,581,582,583,600,601,602,614,615,624,625,630,631,641,663,664,
  665,666,667,668,670,672,680,681,682,683,684,686,687,688,689,690,
  691,692,693,694,695,
  73,96,98,99,772,774,775,777
};

typedef unsigned long long u64;

__device__ __forceinline__ u64 fma2(u64 a, u64 b, u64 c) {
    u64 d;
    asm("fma.rn.f32x2 %0, %1, %2, %3;" : "=l"(d) : "l"(a), "l"(b), "l"(c));
    return d;
}
__device__ __forceinline__ u64 add2(u64 a, u64 b) {
    u64 d;
    asm("add.rn.f32x2 %0, %1, %2;" : "=l"(d) : "l"(a), "l"(b));
    return d;
}
__device__ __forceinline__ u64 pack2(float lo, float hi) {
    u64 d;
    asm("mov.b64 %0, {%1, %2};" : "=l"(d) : "r"(__float_as_uint(lo)), "r"(__float_as_uint(hi)));
    return d;
}
__device__ __forceinline__ void unpack2u(u64 v, unsigned& lo, unsigned& hi) {
    asm("mov.b64 {%0, %1}, %2;" : "=r"(lo), "=r"(hi) : "l"(v));
}
__device__ __forceinline__ float warp_sum(float v) {
#pragma unroll
    for (int o = 16; o > 0; o >>= 1) v += __shfl_down_sync(0xffffffffu, v, o);
    return v;
}
__device__ __forceinline__ float sgnf(float x) {
    return (x > 0.f) ? 1.f : ((x < 0.f) ? -1.f : 0.f);
}

__device__ __forceinline__ void spin_until(unsigned* ctr, unsigned target) {
    while (atomicAdd(ctr, 0u) < target) __nanosleep(200);
}

__global__ void __launch_bounds__(256, 3) k_all(
    const float* __restrict__ recon, const float* __restrict__ gt,
    const float* __restrict__ recon_n, const float* __restrict__ gt_n,
    const float* __restrict__ obj,
    const float* __restrict__ mean, const float* __restrict__ logv,
    const float* __restrict__ vw, float* __restrict__ out)
{
    __shared__ __align__(16) u64 T[PRIOR_PAD][4];
    __shared__ __align__(8) uint2 s_cm[8][FUS_SEGLEN];
    __shared__ float red[8][8];
    const int tid = threadIdx.x;
    const int lane = tid & 31, warp = tid >> 5;
    const float FINF = __int_as_float(0x7F800000);
    const int item = blockIdx.x;

    if (item < PRIOR_ITEMS) {
        // ===== PRIOR: 204 targets, 1024 queries (4/thread) =====
        const int chunk = item % FUS_CHUNKS;
        const int b     = item / FUS_CHUNKS;

        int  jq[4];
        bool aq[4];
        float oxq[4], oyq[4], ozq[4], bqq[4];
        const float* ob = obj + (size_t)b * NO * 3;
#pragma unroll
        for (int q = 0; q < 4; q++) {
            const int j = chunk * 1024 + q * 256 + tid;
            jq[q] = j;
            aq[q] = (j < NO);
            const int jj = aq[q] ? j : (NO - 1);
            oxq[q] = ob[3*jj]; oyq[q] = ob[3*jj+1]; ozq[q] = ob[3*jj+2];
            bqq[q] = 0.5f*(oxq[q]*oxq[q] + oyq[q]*oyq[q] + ozq[q]*ozq[q]);
        }
        const u64 BQ01 = pack2(bqq[0], bqq[1]), NX01 = pack2(-oxq[0], -oxq[1]),
                  NY01 = pack2(-oyq[0], -oyq[1]), NZ01 = pack2(-ozq[0], -ozq[1]);
        const u64 BQ23 = pack2(bqq[2], bqq[3]), NX23 = pack2(-oxq[2], -oxq[3]),
                  NY23 = pack2(-oyq[2], -oyq[3]), NZ23 = pack2(-ozq[2], -ozq[3]);

        const float* rb = recon + (size_t)b * NH * 3;
        if (tid < PRIOR_PAD) {
            float x = 0.f, y = 0.f, z = 0.f, w = FINF;
            if (tid < NPRIOR) {
                const int p = c_prior[tid];
                x = rb[3*p]; y = rb[3*p+1]; z = rb[3*p+2];
                w = 0.5f*(x*x + y*y + z*z);
            }
            float2* pp = (float2*)T[tid];
            pp[0] = make_float2(x, x); pp[1] = make_float2(y, y);
            pp[2] = make_float2(z, z); pp[3] = make_float2(w, w);
        }
        __syncthreads();

        float mp[4] = {FINF, FINF, FINF, FINF};
#pragma unroll 8
        for (int k = 0; k < PRIOR_PAD; k++) {
            const ulonglong2 A  = *(const ulonglong2*)&T[k][0];
            const ulonglong2 Bv = *(const ulonglong2*)&T[k][2];
            u64 M = add2(BQ01, Bv.y);
            M = fma2(NX01, A.x, M); M = fma2(NY01, A.y, M); M = fma2(NZ01, Bv.x, M);
            unsigned u0, u1; unpack2u(M, u0, u1);
            mp[0] = fminf(mp[0], __uint_as_float(u0));
            mp[1] = fminf(mp[1], __uint_as_float(u1));
            M = add2(BQ23, Bv.y);
            M = fma2(NX23, A.x, M); M = fma2(NY23, A.y, M); M = fma2(NZ23, Bv.x, M);
            unpack2u(M, u0, u1);
            mp[2] = fminf(mp[2], __uint_as_float(u0));
            mp[3] = fminf(mp[3], __uint_as_float(u1));
        }
#pragma unroll
        for (int q = 0; q < 4; q++)
            if (aq[q]) g_mp[b * NO + jq[q]] = mp[q];

        __syncthreads();
        if (tid == 0) {
            __threadfence();
            atomicAdd(&g_done_chunk[b * FUS_CHUNKS + chunk], 1u);
        }
    } else if (item < SCAN_ITEMS) {
        // ===== FUSED: row argmin + col min, 4 queries/thread =====
        const int fit   = item - PRIOR_ITEMS;
        const int seg   = fit & 7;
        const int rest  = fit >> 3;
        const int chunk = rest % FUS_CHUNKS;
        const int b     = rest / FUS_CHUNKS;

        int  jq[4];
        bool aq[4];
        u64 BQ[4], NX[4], NY[4], NZ[4];
        const float* ob = obj + (size_t)b * NO * 3;
#pragma unroll
        for (int q = 0; q < 4; q++) {
            const int j = chunk * 1024 + q * 256 + tid;
            jq[q] = j;
            aq[q] = (j < NO);
            const int jj = aq[q] ? j : (NO - 1);
            const float ox = ob[3*jj], oy = ob[3*jj+1], oz = ob[3*jj+2];
            const float bq = 0.5f*(ox*ox + oy*oy + oz*oz);
            BQ[q] = pack2(bq, bq);
            NX[q] = pack2(-ox, -ox);
            NY[q] = pack2(-oy, -oy);
            NZ[q] = pack2(-oz, -oz);
        }

        const float* rb = recon + (size_t)b * NH * 3;
        const float* gb = gt    + (size_t)b * NH * 3;
        const int t0 = seg * FUS_SEGLEN;

        if (tid < FUS_SEGLEN) {
            const int tg = t0 + tid;
            float rx=0.f, ry=0.f, rz=0.f, rw=FINF, gx=0.f, gy=0.f, gz=0.f, gw=FINF;
            if (tg < NH) {
                rx = rb[3*tg]; ry = rb[3*tg+1]; rz = rb[3*tg+2];
                rw = 0.5f*(rx*rx + ry*ry + rz*rz);
                gx = gb[3*tg]; gy = gb[3*tg+1]; gz = gb[3*tg+2];
                gw = 0.5f*(gx*gx + gy*gy + gz*gz);
            }
            float2* pp = (float2*)T[tid];
            pp[0] = make_float2(rx, gx); pp[1] = make_float2(ry, gy);
            pp[2] = make_float2(rz, gz); pp[3] = make_float2(rw, gw);
        }
        __syncthreads();

        unsigned br[4] = {0xFFFFFFFFu, 0xFFFFFFFFu, 0xFFFFFFFFu, 0xFFFFFFFFu};
        unsigned bg[4] = {0xFFFFFFFFu, 0xFFFFFFFFu, 0xFFFFFFFFu, 0xFFFFFFFFu};
#pragma unroll 4
        for (int k = 0; k < FUS_SEGLEN; k++) {
            const ulonglong2 A  = *(const ulonglong2*)&T[k][0];
            const ulonglong2 Bv = *(const ulonglong2*)&T[k][2];
            const unsigned kb = (unsigned)(t0 + k);
            unsigned cr = 0xFFFFFFFFu, cg = 0xFFFFFFFFu;
#pragma unroll
            for (int q = 0; q < 4; q++) {
                u64 M = add2(BQ[q], Bv.y);
                M = fma2(NX[q], A.x, M); M = fma2(NY[q], A.y, M); M = fma2(NZ[q], Bv.x, M);
                unsigned r, g; unpack2u(M, r, g);
                br[q] = min(br[q], (r & 0xFFFFFC00u) | kb);
                bg[q] = min(bg[q], (g & 0xFFFFFC00u) | kb);
                cr = min(cr, r);
                cg = min(cg, g);
            }
            unsigned wr = __reduce_min_sync(0xffffffffu, cr);
            unsigned wg = __reduce_min_sync(0xffffffffu, cg);
            if (lane == 0) s_cm[warp][k] = make_uint2(wr, wg);
        }
#pragma unroll
        for (int q = 0; q < 4; q++) {
            if (aq[q]) {
                atomicMax(&g_okr[b * NO + jq[q]], ~br[q]);
                atomicMax(&g_okg[b * NO + jq[q]], ~bg[q]);
            }
        }

        __syncthreads();
        if (tid < FUS_SEGLEN) {
            uint2 m = s_cm[0][tid];
#pragma unroll
            for (int w = 1; w < 8; w++) {
                uint2 v = s_cm[w][tid];
                m.x = min(m.x, v.x);
                m.y = min(m.y, v.y);
            }
            const int base = b * NT_PAD + t0 + tid;
            atomicMax(&g_cmr[base], ~m.x);
            atomicMax(&g_cmg[base], ~m.y);
        }

        __syncthreads();
        if (tid == 0) {
            __threadfence();
            atomicAdd(&g_done_chunk[b * FUS_CHUNKS + chunk], 1u);
            atomicAdd(&g_done_batch[b], 1u);
        }
    } else if (item < SCAN_ITEMS + OBJ_EPI_ITEMS) {
        // ===== OBJ-EPI consumer: one per (b, chunk); MSE/KLD first, then spin =====
        const int e = item - SCAN_ITEMS;
        const int chunk = e % FUS_CHUNKS;
        const int b     = e / FUS_CHUNKS;

        float a[8] = {0.f,0.f,0.f,0.f,0.f,0.f,0.f,0.f};

        // MSE slice (float4)
        {
            const int base = e * MSE_PER_BLK;
            const int end = min(base + MSE_PER_BLK, MSE_ITEMS);
            if (base + tid < end) {
                const int qq = base + tid;
                const float4 r4 = ((const float4*)recon)[qq];
                const float4 g4 = ((const float4*)gt)[qq];
                float d0 = r4.x - g4.x, d1 = r4.y - g4.y, d2 = r4.z - g4.z, d3 = r4.w - g4.w;
                a[6] = d0*d0 + d1*d1 + d2*d2 + d3*d3;
            }
        }
        // KLD slice
        {
            const int base = e * KLD_PER_BLK;
            const int end = min(base + KLD_PER_BLK, B_ * Z_);
            if (base + tid < end) {
                const int qq = base + tid;
                float m = mean[qq], lv = logv[qq];
                a[7] = 1.f + lv - m * m - expf(lv);
            }
        }

        // spin for chunk completion (8 fused segs + 1 prior)
        if (tid == 0) {
            spin_until(&g_done_chunk[b * FUS_CHUNKS + chunk], 9u);
            g_done_chunk[b * FUS_CHUNKS + chunk] = 0u;   // reset for replay
            __threadfence();
        }
        __syncthreads();

        const float* rb  = recon   + (size_t)b * NH * 3;
        const float* gb  = gt      + (size_t)b * NH * 3;
        const float* rnb = recon_n + (size_t)b * NH * 3;
        const float* gnb = gt_n    + (size_t)b * NH * 3;
        const float* ob  = obj     + (size_t)b * NO * 3;

#pragma unroll
        for (int q = 0; q < 4; q++) {
            const int j = chunk * 1024 + q * 256 + tid;
            if (j >= NO) continue;
            const int idx = b * NO + j;
            const unsigned br = ~g_okr[idx];
            const unsigned bg = ~g_okg[idx];
            const float mp = g_mp[idx];
            g_okr[idx] = 0u;
            g_okg[idx] = 0u;

            const float ox = ob[3*j], oy = ob[3*j+1], oz = ob[3*j+2];
            const int ir = (int)(br & 1023u);
            const int ig = (int)(bg & 1023u);

            float dxr = ox - rb[3*ir], dyr = oy - rb[3*ir+1], dzr = oz - rb[3*ir+2];
            float d2r = dxr*dxr + dyr*dyr + dzr*dzr;
            float dotr = rnb[3*ir]*dxr + rnb[3*ir+1]*dyr + rnb[3*ir+2]*dzr;
            float o2h = sqrtf(d2r) * sgnf(dotr);
            bool interior = (-dotr) > 0.f;

            float dxg = ox - gb[3*ig], dyg = oy - gb[3*ig+1], dzg = oz - gb[3*ig+2];
            float d2g = dxg*dxg + dyg*dyg + dzg*dzg;
            float dotg = gnb[3*ig]*dxg + gnb[3*ig+1]*dyg + gnb[3*ig+2]*dzg;
            float o2h_gt = sqrtf(d2g) * sgnf(dotg);

            float d2p = fmaxf(2.f * mp, 0.f);
            bool cmap  = sqrtf(d2g) < 0.005f;
            bool rcmap = sqrtf(d2r) < 0.005f;

            a[0] += interior ? d2r : 0.f;
            a[1] += cmap ? 1.f : 0.f;
            a[2] += cmap ? d2p : 0.f;
            a[3] += (cmap && rcmap) ? 1.f : 0.f;
            bool w_dist = (o2h_gt < 0.01f) && (o2h_gt > -0.005f);
            float w = (o2h < 0.f) ? 1.5f : (w_dist ? 1.0f : 0.1f);
            a[4] += fabsf(o2h - o2h_gt) * w;
        }

#pragma unroll
        for (int q = 0; q < 8; q++) {
            float v = warp_sum(a[q]);
            if (lane == 0) red[warp][q] = v;
        }
        __syncthreads();
        if (tid < 8) {
            float s = 0.f;
#pragma unroll
            for (int wi = 0; wi < 8; wi++) s += red[wi][tid];
            atomicAdd(&g_acc[tid], (double)s);
        }
    } else {
        // ===== HAND-EPI consumer: one per batch =====
        const int b = item - SCAN_ITEMS - OBJ_EPI_ITEMS;

        if (tid == 0) {
            spin_until(&g_done_batch[b], (unsigned)(FUS_SEGS * FUS_CHUNKS));
            g_done_batch[b] = 0u;   // reset for replay
            __threadfence();
        }
        __syncthreads();

        float s = 0.f;
#pragma unroll
        for (int p = 0; p < 4; p++) {
            const int i = p * 256 + tid;
            if (i >= NT_PAD) continue;
            const int base = b * NT_PAD + i;
            unsigned umr = g_cmr[base], umg = g_cmg[base];
            g_cmr[base] = 0u;
            g_cmg[base] = 0u;
            if (i < NH) {
                float mr = __uint_as_float(~umr);
                float mg = __uint_as_float(~umg);
                float dr = sqrtf(fmaxf(2.f * mr, 0.f));
                float dg = sqrtf(fmaxf(2.f * mg, 0.f));
                s += fabsf(dr - dg) * powf(vw[i], 0.4f);
            }
        }
        float v = warp_sum(s);
        if (lane == 0) red[warp][0] = v;
        __syncthreads();
        if (tid == 0) {
            float t = 0.f;
#pragma unroll
            for (int wi = 0; wi < 8; wi++) t += red[wi][0];
            atomicAdd(&g_acc[5], (double)t);
        }
    }

    // ===== final combine: among the EPI blocks only =====
    if (item >= SCAN_ITEMS) {
        __syncthreads();
        if (tid == 0) {
            __threadfence();
            unsigned t = atomicAdd(&g_ctr, 1u);
            if (t == (unsigned)(EPI_ITEMS - 1)) {
                __threadfence();
                const double KLC = 0.005;
                double recon_loss = g_acc[6] / B_;
                double kld        = -0.5 * g_acc[7] / B_ * 10.0;
                double penetr     = 100.0 * g_acc[0] / B_;
                double npts       = g_acc[1];
                double contact    = 3000.0 * ((npts > 0.0) ? (g_acc[2] / (B_ * npts)) : 0.0);
                double consist    = -5.0 * g_acc[3] / (npts + 0.0001);
                double loss_o     = 30.0 * (1.0 - KLC) * g_acc[4] / ((double)B_ * NO);
                double loss_h     = 35.0 * (1.0 - KLC) * g_acc[5] / ((double)B_ * NH);
                double total = recon_loss + 0.1 * kld + 1000.0 * penetr
                             + 10.0 * contact + 10.0 * consist + (loss_h + loss_o);
                out[0] = (float)total;
#pragma unroll
                for (int q = 0; q < 8; q++) g_acc[q] = 0.0;
                g_ctr = 0u;
            }
        }
    }
}

extern "C" void kernel_launch(void* const* d_in, const int* in_sizes, int n_in,
                              void* d_out, int out_size) {
    const float* recon   = (const float*)d_in[0];
    const float* gt      = (const float*)d_in[1];
    const float* recon_n = (const float*)d_in[2];
    const float* gt_n    = (const float*)d_in[3];
    const float* obj     = (const float*)d_in[4];
    const float* mean    = (const float*)d_in[5];
    const float* logv    = (const float*)d_in[6];
    const float* vw      = (const float*)d_in[7];
    float* out = (float*)d_out;

    k_all<<<TOTAL_ITEMS, 256>>>(recon, gt, recon_n, gt_n, obj, mean, logv, vw, out);
}